// round 11
// baseline (speedup 1.0000x reference)
#include <cuda_runtime.h>
#include <cstdint>
#include <math.h>

#define S_LEN   4096
#define D_DIM   512
#define K_TOT   1536          // 3 taps * 512
#define MAX_OUT 16384

// ---- mma.sync GEMM tiling ----
#define BM 128
#define BN 64
#define BK 32
#define NCHUNK (K_TOT / BK)   // 48
#define AST 36                // smem row stride (floats) for A and B tiles

// smem float offsets
#define OFF_AH 0
#define OFF_AL (BM * AST)                 // 4608
#define OFF_BH (2 * BM * AST)             // 9216
#define OFF_BL (2 * BM * AST + BN * AST)  // 11520
#define SMEM_FLOATS (2 * BM * AST + 2 * BN * AST)   // 13824 -> 55296 bytes
#define SMEM_BYTES (SMEM_FLOATS * 4)

// ---------------- device scratch ----------------
__device__ __align__(16) float g_Wt1[D_DIM * K_TOT];   // [o][k = tap*512 + i]
__device__ __align__(16) float g_Wt2[D_DIM * K_TOT];
__device__ __align__(16) float g_b1[S_LEN * D_DIM];    // conv out (both convs)
__device__ __align__(16) float g_b2[S_LEN * D_DIM];    // ln1+relu out
__device__ __align__(16) int   g_dur[S_LEN];
__device__ __align__(16) int   g_cum[S_LEN];

// ---------------- helpers ----------------
__device__ __forceinline__ void split_tf32(float v, uint32_t& hi, uint32_t& lo) {
    uint32_t h;
    asm("cvt.rna.tf32.f32 %0, %1;" : "=r"(h) : "f"(v));
    float hf = __uint_as_float(h);
    float lf = v - hf;                 // exact residual
    uint32_t l;
    asm("cvt.rna.tf32.f32 %0, %1;" : "=r"(l) : "f"(lf));
    hi = h; lo = l;
}
__device__ __forceinline__ void mma_tf32(float* c,
    uint32_t a0, uint32_t a1, uint32_t a2, uint32_t a3,
    uint32_t b0, uint32_t b1) {
    asm volatile(
        "mma.sync.aligned.m16n8k8.row.col.f32.tf32.tf32.f32 "
        "{%0,%1,%2,%3}, {%4,%5,%6,%7}, {%8,%9}, {%0,%1,%2,%3};"
        : "+f"(c[0]), "+f"(c[1]), "+f"(c[2]), "+f"(c[3])
        : "r"(a0), "r"(a1), "r"(a2), "r"(a3), "r"(b0), "r"(b1));
}

// ---------------- weight transpose: w[o][i][k] -> Wt[o][tap*512+i] ----------------
__global__ void transpose_w_kernel(const float* __restrict__ w1, const float* __restrict__ w2) {
    int idx = blockIdx.x * blockDim.x + threadIdx.x;
    const int n = D_DIM * K_TOT;
    if (idx >= 2 * n) return;
    const float* w  = (idx < n) ? w1 : w2;
    float*       wt = (idx < n) ? g_Wt1 : g_Wt2;
    int j   = (idx < n) ? idx : idx - n;
    int o   = j / K_TOT;
    int r   = j - o * K_TOT;
    int tap = r >> 9;
    int i   = r & 511;
    wt[j] = w[o * 1536 + i * 3 + tap];
}

// ---------------- conv-as-GEMM via mma.sync tf32 (3x split emulated fp32) ----------------
// Y[s,o] = sum_k X'[s,k] * Wt[o,k] + bias[o]
__global__ __launch_bounds__(256, 2) void conv_gemm_mma_kernel(
    const float* __restrict__ enc, const float* __restrict__ bias, int which) {
    extern __shared__ float sm[];
    const float* X  = which ? g_b2  : enc;
    const float* Wt = which ? g_Wt2 : g_Wt1;
    float*       Y  = g_b1;

    const int tid  = threadIdx.x;
    const int wid  = tid >> 5;
    const int lane = tid & 31;
    const int g    = lane >> 2;      // 0..7
    const int cq   = lane & 3;       // 0..3
    const int wm   = wid >> 2;       // 0..1  (64-row slice)
    const int wn   = wid & 3;        // 0..3  (16-col slice)
    const int bm   = blockIdx.y * BM;
    const int bn   = blockIdx.x * BN;

    // loaders
    const int arow = tid >> 1;            // 0..127
    const int ahalf = (tid & 1) * 16;     // k offset 0 or 16
    const int brow = tid >> 2;            // 0..63
    const int bq   = (tid & 3) * 8;       // k offset 0,8,16,24

    float acc[4][2][4];
    #pragma unroll
    for (int i = 0; i < 4; i++)
        #pragma unroll
        for (int j = 0; j < 2; j++)
            #pragma unroll
            for (int q = 0; q < 4; q++) acc[i][j][q] = 0.f;

    float4 a_pre[4];
    float4 b_pre[2];

    auto load_chunk = [&](int c) {
        const int k0  = c * BK;
        const int tap = k0 >> 9;          // constant within chunk
        const int i0  = k0 & 511;
        const int s   = bm + arow + tap - 1;
        if (s >= 0 && s < S_LEN) {
            const float4* p = reinterpret_cast<const float4*>(X + (size_t)s * D_DIM + i0 + ahalf);
            a_pre[0] = p[0]; a_pre[1] = p[1]; a_pre[2] = p[2]; a_pre[3] = p[3];
        } else {
            const float4 z = make_float4(0.f, 0.f, 0.f, 0.f);
            a_pre[0] = z; a_pre[1] = z; a_pre[2] = z; a_pre[3] = z;
        }
        const float4* q = reinterpret_cast<const float4*>(Wt + (size_t)(bn + brow) * K_TOT + k0 + bq);
        b_pre[0] = q[0]; b_pre[1] = q[1];
    };

    auto store_chunk = [&]() {
        // A: 16 floats -> hi/lo at [arow][ahalf..ahalf+15]
        #pragma unroll
        for (int q = 0; q < 4; q++) {
            uint4 h4, l4;
            split_tf32(a_pre[q].x, h4.x, l4.x);
            split_tf32(a_pre[q].y, h4.y, l4.y);
            split_tf32(a_pre[q].z, h4.z, l4.z);
            split_tf32(a_pre[q].w, h4.w, l4.w);
            const int o = arow * AST + ahalf + q * 4;
            *reinterpret_cast<uint4*>(&sm[OFF_AH + o]) = h4;
            *reinterpret_cast<uint4*>(&sm[OFF_AL + o]) = l4;
        }
        // B: 8 floats -> hi/lo at [brow][bq..bq+7]
        #pragma unroll
        for (int q = 0; q < 2; q++) {
            uint4 h4, l4;
            split_tf32(b_pre[q].x, h4.x, l4.x);
            split_tf32(b_pre[q].y, h4.y, l4.y);
            split_tf32(b_pre[q].z, h4.z, l4.z);
            split_tf32(b_pre[q].w, h4.w, l4.w);
            const int o = brow * AST + bq + q * 4;
            *reinterpret_cast<uint4*>(&sm[OFF_BH + o]) = h4;
            *reinterpret_cast<uint4*>(&sm[OFF_BL + o]) = l4;
        }
    };

    load_chunk(0);

    for (int c = 0; c < NCHUNK; c++) {
        store_chunk();
        __syncthreads();
        if (c + 1 < NCHUNK) load_chunk(c + 1);

        #pragma unroll
        for (int ks = 0; ks < 4; ks++) {
            const int kof = ks * 8 + 2 * cq;   // permuted-k float2 base
            // B fragments (2 n-tiles, hi+lo)
            uint32_t bh[2][2], bl[2][2];
            #pragma unroll
            for (int j = 0; j < 2; j++) {
                const int nrow = wn * 16 + j * 8 + g;
                const uint2 vh = *reinterpret_cast<const uint2*>(&sm[OFF_BH + nrow * AST + kof]);
                const uint2 vl = *reinterpret_cast<const uint2*>(&sm[OFF_BL + nrow * AST + kof]);
                bh[j][0] = vh.x; bh[j][1] = vh.y;
                bl[j][0] = vl.x; bl[j][1] = vl.y;
            }
            // A fragments per m-tile; issue 3-split MMAs
            #pragma unroll
            for (int i = 0; i < 4; i++) {
                const int r0 = wm * 64 + i * 16 + g;
                const uint2 h0 = *reinterpret_cast<const uint2*>(&sm[OFF_AH + r0 * AST + kof]);
                const uint2 h1 = *reinterpret_cast<const uint2*>(&sm[OFF_AH + (r0 + 8) * AST + kof]);
                const uint2 l0 = *reinterpret_cast<const uint2*>(&sm[OFF_AL + r0 * AST + kof]);
                const uint2 l1 = *reinterpret_cast<const uint2*>(&sm[OFF_AL + (r0 + 8) * AST + kof]);
                #pragma unroll
                for (int j = 0; j < 2; j++) {
                    mma_tf32(acc[i][j], h0.x, h1.x, h0.y, h1.y, bh[j][0], bh[j][1]);
                    mma_tf32(acc[i][j], h0.x, h1.x, h0.y, h1.y, bl[j][0], bl[j][1]);
                    mma_tf32(acc[i][j], l0.x, l1.x, l0.y, l1.y, bh[j][0], bh[j][1]);
                }
            }
        }
        __syncthreads();
    }

    // ---- epilogue: add bias, store float2 per (tile,row) ----
    #pragma unroll
    for (int i = 0; i < 4; i++) {
        const int row0 = bm + wm * 64 + i * 16 + g;
        #pragma unroll
        for (int j = 0; j < 2; j++) {
            const int col0 = bn + wn * 16 + j * 8 + 2 * cq;
            const float b0 = bias[col0];
            const float b1 = bias[col0 + 1];
            float2 v0 = make_float2(acc[i][j][0] + b0, acc[i][j][1] + b1);
            float2 v1 = make_float2(acc[i][j][2] + b0, acc[i][j][3] + b1);
            *reinterpret_cast<float2*>(Y + (size_t)row0 * D_DIM + col0) = v0;
            *reinterpret_cast<float2*>(Y + (size_t)(row0 + 8) * D_DIM + col0) = v1;
        }
    }
}

__device__ __forceinline__ float warp_allsum(float v) {
    #pragma unroll
    for (int o = 16; o > 0; o >>= 1) v += __shfl_xor_sync(0xffffffffu, v, o);
    return v;
}

// ---------------- LN1 + ReLU:  g_b1 -> g_b2 ----------------
__global__ __launch_bounds__(128) void ln_relu_kernel(
    const float* __restrict__ G, const float* __restrict__ Bt) {
    const int s   = blockIdx.x;
    const int tid = threadIdx.x;
    __shared__ float red1[4], red2[4];

    float4 v = reinterpret_cast<const float4*>(g_b1 + (size_t)s * D_DIM)[tid];
    float p = warp_allsum(v.x + v.y + v.z + v.w);
    const int lane = tid & 31, wid = tid >> 5;
    if (lane == 0) red1[wid] = p;
    __syncthreads();
    const float mean = (red1[0] + red1[1] + red1[2] + red1[3]) * (1.0f / 512.0f);

    float dx = v.x - mean, dy = v.y - mean, dz = v.z - mean, dw = v.w - mean;
    float q = warp_allsum(dx * dx + dy * dy + dz * dz + dw * dw);
    if (lane == 0) red2[wid] = q;
    __syncthreads();
    const float var = (red2[0] + red2[1] + red2[2] + red2[3]) * (1.0f / 512.0f);
    const float inv = rsqrtf(var + 1e-5f);

    const float4 gv = reinterpret_cast<const float4*>(G)[tid];
    const float4 bv = reinterpret_cast<const float4*>(Bt)[tid];
    float4 o;
    o.x = fmaxf(0.f, dx * inv * gv.x + bv.x);
    o.y = fmaxf(0.f, dy * inv * gv.y + bv.y);
    o.z = fmaxf(0.f, dz * inv * gv.z + bv.z);
    o.w = fmaxf(0.f, dw * inv * gv.w + bv.w);
    reinterpret_cast<float4*>(g_b2 + (size_t)s * D_DIM)[tid] = o;
}

// ---------------- LN2 + ReLU + linear + floor(+0.5): g_b1 -> g_dur ----------------
__global__ __launch_bounds__(128) void ln2_lin_kernel(
    const float* __restrict__ G, const float* __restrict__ Bt,
    const float* __restrict__ LW, const float* __restrict__ LB) {
    const int s   = blockIdx.x;
    const int tid = threadIdx.x;
    __shared__ float red1[4], red2[4], red3[4];

    float4 v = reinterpret_cast<const float4*>(g_b1 + (size_t)s * D_DIM)[tid];
    float p = warp_allsum(v.x + v.y + v.z + v.w);
    const int lane = tid & 31, wid = tid >> 5;
    if (lane == 0) red1[wid] = p;
    __syncthreads();
    const float mean = (red1[0] + red1[1] + red1[2] + red1[3]) * (1.0f / 512.0f);

    float dx = v.x - mean, dy = v.y - mean, dz = v.z - mean, dw = v.w - mean;
    float q = warp_allsum(dx * dx + dy * dy + dz * dz + dw * dw);
    if (lane == 0) red2[wid] = q;
    __syncthreads();
    const float var = (red2[0] + red2[1] + red2[2] + red2[3]) * (1.0f / 512.0f);
    const float inv = rsqrtf(var + 1e-5f);

    const float4 gv = reinterpret_cast<const float4*>(G)[tid];
    const float4 bv = reinterpret_cast<const float4*>(Bt)[tid];
    float ox = fmaxf(0.f, dx * inv * gv.x + bv.x);
    float oy = fmaxf(0.f, dy * inv * gv.y + bv.y);
    float oz = fmaxf(0.f, dz * inv * gv.z + bv.z);
    float ow = fmaxf(0.f, dw * inv * gv.w + bv.w);

    const float4 lw = reinterpret_cast<const float4*>(LW)[tid];
    float d = warp_allsum(ox * lw.x + oy * lw.y + oz * lw.z + ow * lw.w);
    if (lane == 0) red3[wid] = d;
    __syncthreads();
    if (tid == 0) {
        float pred = fmaxf(0.f, red3[0] + red3[1] + red3[2] + red3[3] + LB[0]);
        g_dur[s] = (int)floorf(pred + 0.5f);
    }
}

// ---------------- cumsum over 4096 ints ----------------
__global__ __launch_bounds__(512) void cumsum_kernel() {
    __shared__ int wsum[16];
    const int tid  = threadIdx.x;
    const int lane = tid & 31, wid = tid >> 5;

    int vals[8];
    int s = 0;
    #pragma unroll
    for (int j = 0; j < 8; j++) { s += g_dur[tid * 8 + j]; vals[j] = s; }

    int x = s;
    #pragma unroll
    for (int off = 1; off < 32; off <<= 1) {
        int y = __shfl_up_sync(0xffffffffu, x, off);
        if (lane >= off) x += y;
    }
    if (lane == 31) wsum[wid] = x;
    __syncthreads();
    if (wid == 0 && lane < 16) {
        int w = wsum[lane];
        #pragma unroll
        for (int off = 1; off < 16; off <<= 1) {
            int y = __shfl_up_sync(0x0000ffffu, w, off);
            if (lane >= off) w += y;
        }
        wsum[lane] = w;
    }
    __syncthreads();
    const int offset = (wid > 0 ? wsum[wid - 1] : 0) + (x - s);
    #pragma unroll
    for (int j = 0; j < 8; j++) g_cum[tid * 8 + j] = vals[j] + offset;
}

// ---------------- expansion ----------------
__global__ __launch_bounds__(128) void expand_kernel(
    const float* __restrict__ enc, float* __restrict__ out) {
    const int t = blockIdx.x;
    __shared__ int s_idx;
    __shared__ int s_valid;
    if (threadIdx.x == 0) {
        const int total = g_cum[S_LEN - 1];
        int lo = 0;
        #pragma unroll
        for (int step = 2048; step >= 1; step >>= 1) {
            int cand = lo + step;
            if (cand <= S_LEN && g_cum[cand - 1] <= t) lo = cand;
        }
        s_idx = (lo < S_LEN - 1) ? lo : (S_LEN - 1);
        s_valid = (t < total) ? 1 : 0;
    }
    __syncthreads();
    float4 val = make_float4(0.f, 0.f, 0.f, 0.f);
    if (s_valid)
        val = reinterpret_cast<const float4*>(enc + (size_t)s_idx * D_DIM)[threadIdx.x];
    reinterpret_cast<float4*>(out + (size_t)t * D_DIM)[threadIdx.x] = val;
}

// ---------------- optional output_pos tail ----------------
__global__ void pos_tail_kernel(float* __restrict__ out, int base, int n) {
    int i = blockIdx.x * blockDim.x + threadIdx.x;
    if (i < n) out[base + i] = (float)((i % MAX_OUT) + 1);
}

// ---------------- launch ----------------
extern "C" void kernel_launch(void* const* d_in, const int* in_sizes, int n_in,
                              void* d_out, int out_size) {
    const float* enc = (const float*)d_in[0];
    const float* c1w = (const float*)d_in[1];
    const float* c1b = (const float*)d_in[2];
    const float* g1  = (const float*)d_in[3];
    const float* b1  = (const float*)d_in[4];
    const float* c2w = (const float*)d_in[5];
    const float* c2b = (const float*)d_in[6];
    const float* g2  = (const float*)d_in[7];
    const float* b2  = (const float*)d_in[8];
    const float* lw  = (const float*)d_in[9];
    const float* lb  = (const float*)d_in[10];
    float* out = (float*)d_out;

    cudaFuncSetAttribute(conv_gemm_mma_kernel,
                         cudaFuncAttributeMaxDynamicSharedMemorySize, SMEM_BYTES);

    {
        int n = 2 * D_DIM * K_TOT;
        transpose_w_kernel<<<(n + 255) / 256, 256>>>(c1w, c2w);
    }

    dim3 ggrid(D_DIM / BN, S_LEN / BM);   // (8, 32) = 256 CTAs
    conv_gemm_mma_kernel<<<ggrid, 256, SMEM_BYTES>>>(enc, c1b, 0);  // conv1: enc -> g_b1
    ln_relu_kernel<<<S_LEN, 128>>>(g1, b1);                         // g_b1 -> g_b2
    conv_gemm_mma_kernel<<<ggrid, 256, SMEM_BYTES>>>(enc, c2b, 1);  // conv2: g_b2 -> g_b1
    ln2_lin_kernel<<<S_LEN, 128>>>(g2, b2, lw, lb);
    cumsum_kernel<<<1, 512>>>();
    int frames = out_size / D_DIM;
    if (frames > MAX_OUT) frames = MAX_OUT;
    if (frames > 0)
        expand_kernel<<<frames, 128>>>(enc, out);
    int base = frames * D_DIM;
    if (out_size > base) {
        int extra = out_size - base;
        pos_tail_kernel<<<(extra + 255) / 256, 256>>>(out, base, extra);
    }
}

// round 12
// speedup vs baseline: 2.0675x; 2.0675x over previous
#include <cuda_runtime.h>
#include <cstdint>
#include <math.h>

#define S_LEN   4096
#define D_DIM   512
#define K_TOT   1536          // 3 taps * 512
#define MAX_OUT 16384

// ---- mma.sync GEMM tiling ----
#define BM 128
#define BN 128
#define BK 32
#define NCHUNK (K_TOT / BK)   // 48

// interleaved hi/lo row: 32 k * 2 = 64 floats, padded to 80 (stride ≡ 16 mod 32)
#define SMS_BYTES 320                       // 80 floats
#define SM_ABYTES (128 * SMS_BYTES)         // 40960
#define SM_BUF    (2 * SM_ABYTES)           // 81920 per buffer (A + B)
#define SMEM_BYTES (2 * SM_BUF)             // 163840 (double buffered)

// ---------------- device scratch ----------------
__device__ __align__(16) float g_W1s[D_DIM * 2 * K_TOT];   // [o][2k+{hi,lo}]
__device__ __align__(16) float g_W2s[D_DIM * 2 * K_TOT];
__device__ __align__(16) float g_Xs [S_LEN * 2 * D_DIM];   // enc split   [s][2d+{hi,lo}]
__device__ __align__(16) float g_b2s[S_LEN * 2 * D_DIM];   // ln1 out split
__device__ __align__(16) float g_b1 [S_LEN * D_DIM];       // conv out (raw fp32)
__device__ __align__(16) int   g_dur[S_LEN];
__device__ __align__(16) int   g_cum[S_LEN];

// ---------------- helpers ----------------
__device__ __forceinline__ uint32_t smem_u32(const void* p) {
    uint32_t a;
    asm("{ .reg .u64 t; cvta.to.shared.u64 t, %1; cvt.u32.u64 %0, t; }" : "=r"(a) : "l"(p));
    return a;
}
__device__ __forceinline__ void split_tf32(float v, uint32_t& hi, uint32_t& lo) {
    uint32_t h;
    asm("cvt.rna.tf32.f32 %0, %1;" : "=r"(h) : "f"(v));
    float lf = v - __uint_as_float(h);
    uint32_t l;
    asm("cvt.rna.tf32.f32 %0, %1;" : "=r"(l) : "f"(lf));
    hi = h; lo = l;
}
__device__ __forceinline__ void mma_tf32(float* c,
    uint32_t a0, uint32_t a1, uint32_t a2, uint32_t a3,
    uint32_t b0, uint32_t b1) {
    asm volatile(
        "mma.sync.aligned.m16n8k8.row.col.f32.tf32.tf32.f32 "
        "{%0,%1,%2,%3}, {%4,%5,%6,%7}, {%8,%9}, {%0,%1,%2,%3};"
        : "+f"(c[0]), "+f"(c[1]), "+f"(c[2]), "+f"(c[3])
        : "r"(a0), "r"(a1), "r"(a2), "r"(a3), "r"(b0), "r"(b1));
}
__device__ __forceinline__ uint4 lds128(uint32_t addr) {
    uint4 v;
    asm volatile("ld.shared.v4.u32 {%0,%1,%2,%3}, [%4];"
                 : "=r"(v.x), "=r"(v.y), "=r"(v.z), "=r"(v.w) : "r"(addr));
    return v;
}

// ---------------- prep: weights  w[o][i][k] -> Ws[o][2*(tap*512+i)+{hi,lo}] ----------------
__global__ void prep_w_kernel(const float* __restrict__ w1, const float* __restrict__ w2) {
    int idx = blockIdx.x * blockDim.x + threadIdx.x;
    const int n = D_DIM * K_TOT;
    if (idx >= 2 * n) return;
    const float* w  = (idx < n) ? w1 : w2;
    float*       ws = (idx < n) ? g_W1s : g_W2s;
    int j   = (idx < n) ? idx : idx - n;
    int o   = j / K_TOT;
    int r   = j - o * K_TOT;
    int tap = r >> 9;
    int i   = r & 511;
    float v = w[o * 1536 + i * 3 + tap];
    uint32_t h, l;
    split_tf32(v, h, l);
    ws[o * 3072 + 2 * r + 0] = __uint_as_float(h);
    ws[o * 3072 + 2 * r + 1] = __uint_as_float(l);
}

// ---------------- prep: enc -> g_Xs (interleaved hi/lo) ----------------
__global__ void prep_x_kernel(const float* __restrict__ enc) {
    int idx = blockIdx.x * blockDim.x + threadIdx.x;
    if (idx >= S_LEN * D_DIM) return;
    uint32_t h, l;
    split_tf32(enc[idx], h, l);
    g_Xs[2 * idx + 0] = __uint_as_float(h);
    g_Xs[2 * idx + 1] = __uint_as_float(l);
}

// ---------------- conv-as-GEMM via mma.sync tf32 (3x split, pre-split operands) ----------------
// Y[s,o] = sum_k A[s,k] * W[o,k] + bias[o]
__global__ __launch_bounds__(256, 1) void conv_gemm_mma_kernel(
    const float* __restrict__ bias, int which) {
    extern __shared__ char sm[];
    const float* Asrc = which ? g_b2s : g_Xs;
    const float* Bsrc = which ? g_W2s : g_W1s;
    float*       Y    = g_b1;

    const int tid  = threadIdx.x;
    const int wid  = tid >> 5;
    const int lane = tid & 31;
    const int g    = lane >> 2;      // 0..7
    const int cq   = lane & 3;       // 0..3
    const int wm   = wid >> 2;       // 0..1  (64-row slice)
    const int wn   = wid & 3;        // 0..3  (32-col slice)
    const int bm   = blockIdx.y * BM;
    const int bn   = blockIdx.x * BN;

    const uint32_t smb = smem_u32(sm);

    float acc[4][4][4];
    #pragma unroll
    for (int i = 0; i < 4; i++)
        #pragma unroll
        for (int j = 0; j < 4; j++)
            #pragma unroll
            for (int q = 0; q < 4; q++) acc[i][j][q] = 0.f;

    auto copy_chunk = [&](int c, int b) {
        const int k0  = c * BK;
        const int tap = k0 >> 9;            // constant within chunk (512 % 32 == 0)
        const int i0  = k0 & 511;
        const uint32_t bufA = smb + b * SM_BUF;
        const uint32_t bufB = bufA + SM_ABYTES;
        #pragma unroll
        for (int q = 0; q < 8; q++) {       // A: 128 rows x 16 granules
            const int G = tid + 256 * q;
            const int row = G >> 4, c4 = G & 15;
            const int s = bm + row + tap - 1;
            const int ok = (s >= 0 && s < S_LEN);
            const int sc = ok ? s : 0;
            const float* src = Asrc + (size_t)sc * 1024 + 2 * i0 + 4 * c4;
            const uint32_t dst = bufA + row * SMS_BYTES + c4 * 16;
            asm volatile("cp.async.cg.shared.global [%0], [%1], 16, %2;"
                         :: "r"(dst), "l"(src), "r"(ok ? 16 : 0));
        }
        #pragma unroll
        for (int q = 0; q < 8; q++) {       // B: 128 rows x 16 granules
            const int G = tid + 256 * q;
            const int row = G >> 4, c4 = G & 15;
            const float* src = Bsrc + (size_t)(bn + row) * 3072 + 2 * k0 + 4 * c4;
            const uint32_t dst = bufB + row * SMS_BYTES + c4 * 16;
            asm volatile("cp.async.cg.shared.global [%0], [%1], 16;"
                         :: "r"(dst), "l"(src));
        }
        asm volatile("cp.async.commit_group;" ::: "memory");
    };

    copy_chunk(0, 0);

    for (int c = 0; c < NCHUNK; c++) {
        const int b = c & 1;
        if (c + 1 < NCHUNK) {
            copy_chunk(c + 1, b ^ 1);
            asm volatile("cp.async.wait_group 1;" ::: "memory");
        } else {
            asm volatile("cp.async.wait_group 0;" ::: "memory");
        }
        __syncthreads();

        const uint32_t bufA = smb + b * SM_BUF;
        const uint32_t bufB = bufA + SM_ABYTES;

        #pragma unroll
        for (int ks = 0; ks < 4; ks++) {
            const uint32_t kb = (uint32_t)(ks * 64 + cq * 16);   // byte offset of (hi,lo,hi,lo)
            uint4 bw[4];
            #pragma unroll
            for (int j = 0; j < 4; j++) {
                const int nrow = wn * 32 + j * 8 + g;
                bw[j] = lds128(bufB + nrow * SMS_BYTES + kb);
            }
            #pragma unroll
            for (int i = 0; i < 4; i++) {
                const int r0 = wm * 64 + i * 16 + g;
                const uint4 v0 = lds128(bufA + r0 * SMS_BYTES + kb);
                const uint4 v1 = lds128(bufA + (r0 + 8) * SMS_BYTES + kb);
                #pragma unroll
                for (int j = 0; j < 4; j++) {
                    mma_tf32(acc[i][j], v0.x, v1.x, v0.z, v1.z, bw[j].x, bw[j].z); // hi*hi
                    mma_tf32(acc[i][j], v0.x, v1.x, v0.z, v1.z, bw[j].y, bw[j].w); // hi*lo
                    mma_tf32(acc[i][j], v0.y, v1.y, v0.w, v1.w, bw[j].x, bw[j].z); // lo*hi
                }
            }
        }
        __syncthreads();
    }

    // ---- epilogue: add bias, store ----
    #pragma unroll
    for (int i = 0; i < 4; i++) {
        const int row0 = bm + wm * 64 + i * 16 + g;
        #pragma unroll
        for (int j = 0; j < 4; j++) {
            const int col = bn + wn * 32 + j * 8 + 2 * cq;
            const float b0 = bias[col];
            const float b1 = bias[col + 1];
            *reinterpret_cast<float2*>(Y + (size_t)row0 * D_DIM + col) =
                make_float2(acc[i][j][0] + b0, acc[i][j][1] + b1);
            *reinterpret_cast<float2*>(Y + (size_t)(row0 + 8) * D_DIM + col) =
                make_float2(acc[i][j][2] + b0, acc[i][j][3] + b1);
        }
    }
}

__device__ __forceinline__ float warp_allsum(float v) {
    #pragma unroll
    for (int o = 16; o > 0; o >>= 1) v += __shfl_xor_sync(0xffffffffu, v, o);
    return v;
}

// ---------------- LN1 + ReLU: g_b1 -> g_b2s (split interleaved) ----------------
__global__ __launch_bounds__(128) void ln_relu_kernel(
    const float* __restrict__ G, const float* __restrict__ Bt) {
    const int s   = blockIdx.x;
    const int tid = threadIdx.x;
    __shared__ float red1[4], red2[4];

    float4 v = reinterpret_cast<const float4*>(g_b1 + (size_t)s * D_DIM)[tid];
    float p = warp_allsum(v.x + v.y + v.z + v.w);
    const int lane = tid & 31, wid = tid >> 5;
    if (lane == 0) red1[wid] = p;
    __syncthreads();
    const float mean = (red1[0] + red1[1] + red1[2] + red1[3]) * (1.0f / 512.0f);

    float dx = v.x - mean, dy = v.y - mean, dz = v.z - mean, dw = v.w - mean;
    float q = warp_allsum(dx * dx + dy * dy + dz * dz + dw * dw);
    if (lane == 0) red2[wid] = q;
    __syncthreads();
    const float var = (red2[0] + red2[1] + red2[2] + red2[3]) * (1.0f / 512.0f);
    const float inv = rsqrtf(var + 1e-5f);

    const float4 gv = reinterpret_cast<const float4*>(G)[tid];
    const float4 bv = reinterpret_cast<const float4*>(Bt)[tid];
    float o0 = fmaxf(0.f, dx * inv * gv.x + bv.x);
    float o1 = fmaxf(0.f, dy * inv * gv.y + bv.y);
    float o2 = fmaxf(0.f, dz * inv * gv.z + bv.z);
    float o3 = fmaxf(0.f, dw * inv * gv.w + bv.w);

    uint4 u0, u1;
    split_tf32(o0, u0.x, u0.y);
    split_tf32(o1, u0.z, u0.w);
    split_tf32(o2, u1.x, u1.y);
    split_tf32(o3, u1.z, u1.w);
    uint4* dst = reinterpret_cast<uint4*>(g_b2s + (size_t)s * 1024 + 8 * tid);
    dst[0] = u0;
    dst[1] = u1;
}

// ---------------- LN2 + ReLU + linear + floor(+0.5): g_b1 -> g_dur ----------------
__global__ __launch_bounds__(128) void ln2_lin_kernel(
    const float* __restrict__ G, const float* __restrict__ Bt,
    const float* __restrict__ LW, const float* __restrict__ LB) {
    const int s   = blockIdx.x;
    const int tid = threadIdx.x;
    __shared__ float red1[4], red2[4], red3[4];

    float4 v = reinterpret_cast<const float4*>(g_b1 + (size_t)s * D_DIM)[tid];
    float p = warp_allsum(v.x + v.y + v.z + v.w);
    const int lane = tid & 31, wid = tid >> 5;
    if (lane == 0) red1[wid] = p;
    __syncthreads();
    const float mean = (red1[0] + red1[1] + red1[2] + red1[3]) * (1.0f / 512.0f);

    float dx = v.x - mean, dy = v.y - mean, dz = v.z - mean, dw = v.w - mean;
    float q = warp_allsum(dx * dx + dy * dy + dz * dz + dw * dw);
    if (lane == 0) red2[wid] = q;
    __syncthreads();
    const float var = (red2[0] + red2[1] + red2[2] + red2[3]) * (1.0f / 512.0f);
    const float inv = rsqrtf(var + 1e-5f);

    const float4 gv = reinterpret_cast<const float4*>(G)[tid];
    const float4 bv = reinterpret_cast<const float4*>(Bt)[tid];
    float ox = fmaxf(0.f, dx * inv * gv.x + bv.x);
    float oy = fmaxf(0.f, dy * inv * gv.y + bv.y);
    float oz = fmaxf(0.f, dz * inv * gv.z + bv.z);
    float ow = fmaxf(0.f, dw * inv * gv.w + bv.w);

    const float4 lw = reinterpret_cast<const float4*>(LW)[tid];
    float d = warp_allsum(ox * lw.x + oy * lw.y + oz * lw.z + ow * lw.w);
    if (lane == 0) red3[wid] = d;
    __syncthreads();
    if (tid == 0) {
        float pred = fmaxf(0.f, red3[0] + red3[1] + red3[2] + red3[3] + LB[0]);
        g_dur[s] = (int)floorf(pred + 0.5f);
    }
}

// ---------------- cumsum over 4096 ints ----------------
__global__ __launch_bounds__(512) void cumsum_kernel() {
    __shared__ int wsum[16];
    const int tid  = threadIdx.x;
    const int lane = tid & 31, wid = tid >> 5;

    int vals[8];
    int s = 0;
    #pragma unroll
    for (int j = 0; j < 8; j++) { s += g_dur[tid * 8 + j]; vals[j] = s; }

    int x = s;
    #pragma unroll
    for (int off = 1; off < 32; off <<= 1) {
        int y = __shfl_up_sync(0xffffffffu, x, off);
        if (lane >= off) x += y;
    }
    if (lane == 31) wsum[wid] = x;
    __syncthreads();
    if (wid == 0 && lane < 16) {
        int w = wsum[lane];
        #pragma unroll
        for (int off = 1; off < 16; off <<= 1) {
            int y = __shfl_up_sync(0x0000ffffu, w, off);
            if (lane >= off) w += y;
        }
        wsum[lane] = w;
    }
    __syncthreads();
    const int offset = (wid > 0 ? wsum[wid - 1] : 0) + (x - s);
    #pragma unroll
    for (int j = 0; j < 8; j++) g_cum[tid * 8 + j] = vals[j] + offset;
}

// ---------------- expansion ----------------
__global__ __launch_bounds__(128) void expand_kernel(
    const float* __restrict__ enc, float* __restrict__ out) {
    const int t = blockIdx.x;
    __shared__ int s_idx;
    __shared__ int s_valid;
    if (threadIdx.x == 0) {
        const int total = g_cum[S_LEN - 1];
        int lo = 0;
        #pragma unroll
        for (int step = 2048; step >= 1; step >>= 1) {
            int cand = lo + step;
            if (cand <= S_LEN && g_cum[cand - 1] <= t) lo = cand;
        }
        s_idx = (lo < S_LEN - 1) ? lo : (S_LEN - 1);
        s_valid = (t < total) ? 1 : 0;
    }
    __syncthreads();
    float4 val = make_float4(0.f, 0.f, 0.f, 0.f);
    if (s_valid)
        val = reinterpret_cast<const float4*>(enc + (size_t)s_idx * D_DIM)[threadIdx.x];
    reinterpret_cast<float4*>(out + (size_t)t * D_DIM)[threadIdx.x] = val;
}

// ---------------- optional output_pos tail ----------------
__global__ void pos_tail_kernel(float* __restrict__ out, int base, int n) {
    int i = blockIdx.x * blockDim.x + threadIdx.x;
    if (i < n) out[base + i] = (float)((i % MAX_OUT) + 1);
}

// ---------------- launch ----------------
extern "C" void kernel_launch(void* const* d_in, const int* in_sizes, int n_in,
                              void* d_out, int out_size) {
    const float* enc = (const float*)d_in[0];
    const float* c1w = (const float*)d_in[1];
    const float* c1b = (const float*)d_in[2];
    const float* g1  = (const float*)d_in[3];
    const float* b1  = (const float*)d_in[4];
    const float* c2w = (const float*)d_in[5];
    const float* c2b = (const float*)d_in[6];
    const float* g2  = (const float*)d_in[7];
    const float* b2  = (const float*)d_in[8];
    const float* lw  = (const float*)d_in[9];
    const float* lb  = (const float*)d_in[10];
    float* out = (float*)d_out;

    cudaFuncSetAttribute(conv_gemm_mma_kernel,
                         cudaFuncAttributeMaxDynamicSharedMemorySize, SMEM_BYTES);

    {
        int n = 2 * D_DIM * K_TOT;
        prep_w_kernel<<<(n + 255) / 256, 256>>>(c1w, c2w);
        int m = S_LEN * D_DIM;
        prep_x_kernel<<<(m + 255) / 256, 256>>>(enc);
    }

    dim3 ggrid(D_DIM / BN, S_LEN / BM);   // (4, 32) = 128 CTAs
    conv_gemm_mma_kernel<<<ggrid, 256, SMEM_BYTES>>>(c1b, 0);   // conv1: g_Xs  -> g_b1
    ln_relu_kernel<<<S_LEN, 128>>>(g1, b1);                     // g_b1 -> g_b2s (split)
    conv_gemm_mma_kernel<<<ggrid, 256, SMEM_BYTES>>>(c2b, 1);   // conv2: g_b2s -> g_b1
    ln2_lin_kernel<<<S_LEN, 128>>>(g2, b2, lw, lb);
    cumsum_kernel<<<1, 512>>>();
    int frames = out_size / D_DIM;
    if (frames > MAX_OUT) frames = MAX_OUT;
    if (frames > 0)
        expand_kernel<<<frames, 128>>>(enc, out);
    int base = frames * D_DIM;
    if (out_size > base) {
        int extra = out_size - base;
        pos_tail_kernel<<<(extra + 255) / 256, 256>>>(out, base, extra);
    }
}